// round 16
// baseline (speedup 1.0000x reference)
#include <cuda_runtime.h>
#include <cuda_fp16.h>
#include <math.h>
#include <stdint.h>

// Problem constants
#define BSZ  16384
#define HD   256
#define GXD  70
#define GYD  70
#define SWIN 2
#define NKW  25   // 5x5 window

// ---------------- scratch (static device memory, no allocations) ----------------
// g_AH row (512): [featHi(256) | hidHi(256)]
// g_W1 row jn=4u+g (512): [WihHi | WhhHi] of orig row g*256+u (gate-interleaved)
// g_Waux: w_hh n-gate rows (512+u), hi only (256 x 256)
// g_Cext row (1024): [mixHi|qHi|mixLo|qLo]; GEMM2 reads cols [0,512)
__device__ __align__(16) __half g_AH  [(size_t)BSZ * 512];
__device__ __align__(16) __half g_W1  [(size_t)1024 * 512];
__device__ __align__(16) __half g_Waux[(size_t)256 * 256];
__device__ __align__(16) __half g_Wout[(size_t)256 * 512];
__device__ __align__(16) __half g_Cext[(size_t)BSZ * 1024];
__device__ float g_hn[(size_t)BSZ * 256];   // hidden @ w_hh[n]^T + b_hh[n]
__device__ float g_sg[(size_t)BSZ * 256];
__device__ float g_ug[(size_t)BSZ * 256];
__device__ float g_bc[1024];                // b_ih+b_hh, gate-interleaved order

__device__ __forceinline__ float sigmoidf_(float x) {
    return 1.0f / (1.0f + expf(-x));
}

__device__ __forceinline__ uint32_t smem_u32(const void* p) {
    uint32_t a;
    asm("{ .reg .u64 t; cvta.to.shared.u64 t, %1; cvt.u32.u64 %0, t; }" : "=r"(a) : "l"(p));
    return a;
}

__device__ __forceinline__ void ldsm_x4(uint32_t addr, uint32_t& r0, uint32_t& r1,
                                        uint32_t& r2, uint32_t& r3) {
    asm volatile("ldmatrix.sync.aligned.m8n8.x4.shared.b16 {%0,%1,%2,%3}, [%4];"
                 : "=r"(r0), "=r"(r1), "=r"(r2), "=r"(r3) : "r"(addr));
}

__device__ __forceinline__ void mma16816(float& d0, float& d1, float& d2, float& d3,
                                         uint32_t a0, uint32_t a1, uint32_t a2, uint32_t a3,
                                         uint32_t b0, uint32_t b1) {
    asm volatile("mma.sync.aligned.m16n8k16.row.col.f32.f16.f16.f32 "
                 "{%0,%1,%2,%3}, {%4,%5,%6,%7}, {%8,%9}, {%0,%1,%2,%3};"
                 : "+f"(d0), "+f"(d1), "+f"(d2), "+f"(d3)
                 : "r"(a0), "r"(a1), "r"(a2), "r"(a3), "r"(b0), "r"(b1));
}

#define CP_ASYNC16(dst, src) \
    asm volatile("cp.async.cg.shared.global [%0], [%1], 16;" :: "r"(dst), "l"(src))
#define CP_COMMIT() asm volatile("cp.async.commit_group;")
#define CP_WAIT2()  asm volatile("cp.async.wait_group 2;")

// Swizzled tile: 128 rows x 128B (64 halves), unit' = unit ^ (row&7). 16KB/tile.
#define TILEB   16384
#define STAGEB  32768   // A tile + B tile
#define NSTAGE  3
#define SMEM_BYTES (NSTAGE * STAGEB)

// ---------------- conversion kernels (fp32 -> fp16 hi) --------------------------
// z=0: feat -> g_AH cols [0,256); z=1: hidden -> g_AH cols [256,512)
__global__ __launch_bounds__(256) void conv_ah_kernel(const float* __restrict__ input_tensor,
                                                      const float* __restrict__ hidden) {
    size_t i = (size_t)blockIdx.x * 256 + threadIdx.x;   // BSZ*128 threads, 2 cols each
    size_t b = i >> 7;
    int c = (int)(i & 127) * 2;
    const float* src; int stride, base;
    if (blockIdx.z == 0) { src = input_tensor; stride = 258; base = 0;   }
    else                 { src = hidden;       stride = 256; base = 256; }
    float2 v = *(const float2*)(src + b * stride + c);
    __half2 hh;
    hh.x = __float2half(v.x);
    hh.y = __float2half(v.y);
    *(__half2*)(g_AH + b * 512 + base + c) = hh;
}

// z=0: w_ih -> g_W1[:,0:256) interleaved rows; z=1: w_hh -> g_W1[:,256:512);
// z=2: w_out -> g_Wout; z=3: w_hh n-rows -> g_Waux
__global__ __launch_bounds__(256) void conv_w_kernel(const float* __restrict__ w_ih,
                                                     const float* __restrict__ w_hh,
                                                     const float* __restrict__ w_out) {
    const int sel = blockIdx.z;
    size_t e = ((size_t)blockIdx.x * 256 + threadIdx.x) * 2;
    if (sel <= 1) {
        if (blockIdx.x >= 512) return;
        int rn = (int)(e >> 8), k = (int)(e & 255);
        int orig = (rn & 3) * 256 + (rn >> 2);
        const float* src = ((sel == 0) ? w_ih : w_hh) + (size_t)orig * 256 + k;
        float2 v = *(const float2*)src;
        __half2 hh; hh.x = __float2half(v.x); hh.y = __float2half(v.y);
        *(__half2*)(g_W1 + (size_t)rn * 512 + (sel ? 256 : 0) + k) = hh;
    } else if (sel == 2) {
        if (blockIdx.x >= 256) return;   // 256*512 elems
        float2 v = *(const float2*)(w_out + e);
        __half2 hh; hh.x = __float2half(v.x); hh.y = __float2half(v.y);
        *(__half2*)(g_Wout + e) = hh;
    } else {
        if (blockIdx.x >= 128) return;   // 256*256 elems
        float2 v = *(const float2*)(w_hh + (size_t)512 * 256 + e);
        __half2 hh; hh.x = __float2half(v.x); hh.y = __float2half(v.y);
        *(__half2*)(g_Waux + e) = hh;
    }
}

__global__ void conv_bias_kernel(const float* __restrict__ b_ih,
                                 const float* __restrict__ b_hh) {
    int jn = blockIdx.x * 256 + threadIdx.x;
    int orig = (jn & 3) * 256 + (jn >> 2);
    g_bc[jn] = b_ih[orig] + b_hh[orig];
}

// ---------------- pipelined mma.sync GEMM mainloop (R15-proven) -----------------
// 128 threads, 4 warps in 2(m) x 2(n); warp tile 64x64; CTA tile 128x128.
template <int KEXT>
__device__ __forceinline__ void mma_gemm_main(const __half* __restrict__ A, int lda,
                                              const __half* __restrict__ W, int ldw,
                                              char* smem, float (&acc)[4][8][4]) {
    const int tid = threadIdx.x;
    const int wid = tid >> 5, lane = tid & 31;
    const int wm = (wid & 1) * 64;
    const int wn = (wid >> 1) * 64;
    const uint32_t sbase = smem_u32(smem);

    const int crow0 = tid >> 3, cunit = tid & 7;
    const __half* ga = A + (size_t)(blockIdx.y * 128) * lda + cunit * 8;
    const __half* gw = W + (size_t)(blockIdx.x * 128) * ldw + cunit * 8;

    int rowA[4], rowB[4];
#pragma unroll
    for (int mt = 0; mt < 4; mt++)
        rowA[mt] = wm + mt * 16 + (lane & 8) + (lane & 7);
#pragma unroll
    for (int nt2 = 0; nt2 < 4; nt2++)
        rowB[nt2] = wn + nt2 * 16 + ((lane >> 4) & 1) * 8 + (lane & 7);
    const int uA = lane >> 4;
    const int uB = (lane >> 3) & 1;

    constexpr int NC = KEXT / 64;

    auto issue = [&](int ch) {
        const int s = ch % NSTAGE;
        const uint32_t dA = sbase + s * STAGEB;
        const uint32_t dB = dA + TILEB;
#pragma unroll
        for (int j = 0; j < 8; j++) {
            const int row = crow0 + j * 16;
            const uint32_t off = (uint32_t)row * 128 + (uint32_t)((cunit ^ (row & 7)) * 16);
            CP_ASYNC16(dA + off, ga + (size_t)row * lda + ch * 64);
            CP_ASYNC16(dB + off, gw + (size_t)row * ldw + ch * 64);
        }
        CP_COMMIT();
    };

    issue(0);
    issue(1);
#pragma unroll 1
    for (int ch = 0; ch < NC; ch++) {
        if (ch + 2 < NC) issue(ch + 2); else CP_COMMIT();
        CP_WAIT2();
        __syncthreads();
        const int s = ch % NSTAGE;
        const uint32_t aB = sbase + s * STAGEB;
        const uint32_t bB = aB + TILEB;
#pragma unroll
        for (int ks = 0; ks < 4; ks++) {
            uint32_t a[4][4], b[4][4];
#pragma unroll
            for (int mt = 0; mt < 4; mt++) {
                const int u = ks * 2 + uA;
                const uint32_t addr = aB + (uint32_t)rowA[mt] * 128
                                    + (uint32_t)((u ^ (rowA[mt] & 7)) * 16);
                ldsm_x4(addr, a[mt][0], a[mt][1], a[mt][2], a[mt][3]);
            }
#pragma unroll
            for (int nt2 = 0; nt2 < 4; nt2++) {
                const int u = ks * 2 + uB;
                const uint32_t addr = bB + (uint32_t)rowB[nt2] * 128
                                    + (uint32_t)((u ^ (rowB[nt2] & 7)) * 16);
                ldsm_x4(addr, b[nt2][0], b[nt2][1], b[nt2][2], b[nt2][3]);
            }
#pragma unroll
            for (int mt = 0; mt < 4; mt++)
#pragma unroll
                for (int nt = 0; nt < 8; nt++) {
                    const uint32_t b0 = b[nt >> 1][(nt & 1) * 2 + 0];
                    const uint32_t b1 = b[nt >> 1][(nt & 1) * 2 + 1];
                    mma16816(acc[mt][nt][0], acc[mt][nt][1], acc[mt][nt][2], acc[mt][nt][3],
                             a[mt][0], a[mt][1], a[mt][2], a[mt][3], b0, b1);
                }
        }
        __syncthreads();
    }
}

// ---------------- aux GEMM: h_n = hidden @ w_hh[n]^T + b_hh[n] ------------------
__global__ __launch_bounds__(128) void aux_gemm_kernel(const float* __restrict__ b_hh) {
    extern __shared__ char smem[];
    float acc[4][8][4];
#pragma unroll
    for (int mt = 0; mt < 4; mt++)
#pragma unroll
        for (int nt = 0; nt < 8; nt++)
#pragma unroll
            for (int e = 0; e < 4; e++) acc[mt][nt][e] = 0.0f;

    mma_gemm_main<256>(g_AH + 256, 512, g_Waux, 256, smem, acc);

    const int wid = threadIdx.x >> 5, lane = threadIdx.x & 31;
    const int wm = (wid & 1) * 64, wn = (wid >> 1) * 64;
    const int gid = lane >> 2, tig = lane & 3;
#pragma unroll
    for (int mt = 0; mt < 4; mt++) {
        const int r = blockIdx.y * 128 + wm + mt * 16 + gid;
#pragma unroll
        for (int nt = 0; nt < 8; nt++) {
            const int c = blockIdx.x * 128 + wn + nt * 8 + 2 * tig;
            float2 bv = *(const float2*)(b_hh + 512 + c);
            float2 v0 = { acc[mt][nt][0] + bv.x, acc[mt][nt][1] + bv.y };
            float2 v1 = { acc[mt][nt][2] + bv.x, acc[mt][nt][3] + bv.y };
            *(float2*)(g_hn + (size_t)r * 256 + c)       = v0;
            *(float2*)(g_hn + (size_t)(r + 8) * 256 + c) = v1;
        }
    }
}

// ---------------- combined GEMM: gate sums + fused gate math --------------------
__global__ __launch_bounds__(128) void tgemm1_kernel() {
    extern __shared__ char smem[];
    float acc[4][8][4];
#pragma unroll
    for (int mt = 0; mt < 4; mt++)
#pragma unroll
        for (int nt = 0; nt < 8; nt++)
#pragma unroll
            for (int e = 0; e < 4; e++) acc[mt][nt][e] = 0.0f;

    mma_gemm_main<512>(g_AH, 512, g_W1, 512, smem, acc);
    __syncthreads();   // mainloop drained; smem free for staging

    __half* qh_s = (__half*)smem;                 // [128][32]
    __half* ql_s = qh_s + 4096;                   // [128][32]
    float* sg_s = (float*)(smem + 16384);         // [128][32]
    float* ug_s = sg_s + 4096;                    // [128][32]

    const int tid = threadIdx.x, wid = tid >> 5, lane = tid & 31;
    const int wm = (wid & 1) * 64, wn = (wid >> 1) * 64;
    const int gid = lane >> 2, tig = lane & 3;
    const int srcLane = lane & ~1;
#pragma unroll
    for (int mt = 0; mt < 4; mt++) {
#pragma unroll
        for (int nt = 0; nt < 8; nt++) {
            const int col = wn + nt * 8 + 2 * tig;           // 0..127 tile-local
            const float bc0 = g_bc[blockIdx.x * 128 + col];
            const float bc1 = g_bc[blockIdx.x * 128 + col + 1];
#pragma unroll
            for (int half = 0; half < 2; half++) {
                const int rl = wm + mt * 16 + gid + half * 8;  // 0..127
                float v0 = acc[mt][nt][half * 2 + 0] + bc0;
                float v1 = acc[mt][nt][half * 2 + 1] + bc1;
                float sig0 = sigmoidf_(v0);
                float sig1 = sigmoidf_(v1);
                float rg = __shfl_sync(0xffffffffu, sig0, srcLane);
                float ug = __shfl_sync(0xffffffffu, sig1, srcLane);
                if (tig & 1) {   // this thread's even col is the n-gate of unit ul
                    const int ul = col >> 2;                   // 0..31
                    const size_t r = (size_t)(blockIdx.y * 128 + rl);
                    float hn = g_hn[r * 256 + blockIdx.x * 32 + ul];
                    float q  = tanhf(v0 + (rg - 1.0f) * hn);
                    __half qh = __float2half(q);
                    qh_s[rl * 32 + ul] = qh;
                    ql_s[rl * 32 + ul] = __float2half(q - __half2float(qh));
                    sg_s[rl * 32 + ul] = sig1;   // spatialgate
                    ug_s[rl * 32 + ul] = ug;     // updategate
                }
            }
        }
    }
    __syncthreads();
    // coalesced-ish global writes
    for (int idx = tid; idx < 4096; idx += 128) {
        const int rl = idx >> 5, ul = idx & 31;
        const size_t r = (size_t)(blockIdx.y * 128 + rl);
        const int u = blockIdx.x * 32 + ul;
        g_Cext[r * 1024 + 256 + u] = qh_s[idx];
        g_Cext[r * 1024 + 768 + u] = ql_s[idx];
        g_sg[r * 256 + u] = sg_s[idx];
        g_ug[r * 256 + u] = ug_s[idx];
    }
}

// ---------------- kernel: attention over 5x5 context (R12 gather, no gates) -----
__global__ __launch_bounds__(256) void phaseB_kernel(
    const float* __restrict__ input_tensor,
    const float* __restrict__ memory) {
    const int b = blockIdx.x;
    const int t = threadIdx.x;

    __shared__ __align__(16) float q_s[HD];
    __shared__ __align__(16) float attn_p[NKW][2];
    __shared__ __align__(16) float w_s[NKW];
    __shared__ __align__(16) float mixp[4][HD];

    __half* crow = g_Cext + (size_t)b * 1024;
    float q = __half2float(crow[256 + t]) + __half2float(crow[768 + t]);
    q_s[t] = q;

    int gx = (int)input_tensor[(size_t)b * 258 + 256] + SWIN;
    int gy = (int)input_tensor[(size_t)b * 258 + 257] + SWIN;
    gx = min(max(gx, 0), GXD - 1);
    gy = min(max(gy, 0), GYD - 1);

    __syncthreads();   // q_s ready

    // pass 1: fused gather + partial attention dot (float4); 64 threads per k-row
    const int kq  = t >> 6;
    const int cq  = (t & 63) * 4;
    const int lane = t & 31;
    const int sub  = (t >> 5) & 1;
    float4 q4 = *(const float4*)(q_s + cq);
#pragma unroll
    for (int base = 0; base < 28; base += 4) {
        const int k = base + kq;
        if (k < NKW) {               // uniform per warp
            int xi = min(max(gx + k / 5 - SWIN, 0), GXD - 1);
            int yi = min(max(gy + k % 5 - SWIN, 0), GYD - 1);
            float4 v = *(const float4*)(memory + ((size_t)xi * GYD + yi) * HD + cq);
            float part = v.x * q4.x + v.y * q4.y + v.z * q4.z + v.w * q4.w;
#pragma unroll
            for (int off = 16; off; off >>= 1)
                part += __shfl_xor_sync(0xffffffffu, part, off);
            if (lane == 0) attn_p[k][sub] = part;
        }
    }
    __syncthreads();

    // softmax over 25 (one warp), attn==0 -> -inf, NaN -> 0 semantics
    if (t < 32) {
        float v = (lane < NKW) ? (attn_p[lane][0] + attn_p[lane][1]) : -INFINITY;
        if (v == 0.0f) v = -INFINITY;
        float mx = v;
#pragma unroll
        for (int off = 16; off; off >>= 1)
            mx = fmaxf(mx, __shfl_xor_sync(0xffffffffu, mx, off));
        float e = (mx == -INFINITY) ? 0.0f : expf(v - mx);
        float den = e;
#pragma unroll
        for (int off = 16; off; off >>= 1)
            den += __shfl_xor_sync(0xffffffffu, den, off);
        float wv = (den > 0.0f) ? (e / den) : 0.0f;
        if (lane < NKW) w_s[lane] = wv;
    }
    __syncthreads();

    // pass 2: re-gather + weighted mix partials per k-group
    {
        float4 m4 = make_float4(0.0f, 0.0f, 0.0f, 0.0f);
#pragma unroll
        for (int base = 0; base < 28; base += 4) {
            const int k = base + kq;
            if (k < NKW) {
                int xi = min(max(gx + k / 5 - SWIN, 0), GXD - 1);
                int yi = min(max(gy + k % 5 - SWIN, 0), GYD - 1);
                float4 v = *(const float4*)(memory + ((size_t)xi * GYD + yi) * HD + cq);
                const float w = w_s[k];
                m4.x = fmaf(w, v.x, m4.x);
                m4.y = fmaf(w, v.y, m4.y);
                m4.z = fmaf(w, v.z, m4.z);
                m4.w = fmaf(w, v.w, m4.w);
            }
        }
        *(float4*)(&mixp[kq][cq]) = m4;
    }
    __syncthreads();

    // combine 4 k-group partials (64 threads) and write mix split
    if (t < 64) {
        const int c0 = t * 4;
        float4 a0 = *(const float4*)(&mixp[0][c0]);
        float4 a1 = *(const float4*)(&mixp[1][c0]);
        float4 a2 = *(const float4*)(&mixp[2][c0]);
        float4 a3 = *(const float4*)(&mixp[3][c0]);
        float mv[4] = { a0.x + a1.x + a2.x + a3.x,
                        a0.y + a1.y + a2.y + a3.y,
                        a0.z + a1.z + a2.z + a3.z,
                        a0.w + a1.w + a2.w + a3.w };
        __half mh[4], ml[4];
#pragma unroll
        for (int e = 0; e < 4; e++) {
            mh[e] = __float2half(mv[e]);
            ml[e] = __float2half(mv[e] - __half2float(mh[e]));
        }
        __half2 h01; h01.x = mh[0]; h01.y = mh[1];
        __half2 h23; h23.x = mh[2]; h23.y = mh[3];
        __half2 l01; l01.x = ml[0]; l01.y = ml[1];
        __half2 l23; l23.x = ml[2]; l23.y = ml[3];
        *(__half2*)(crow + c0)           = h01;   // mixHi
        *(__half2*)(crow + c0 + 2)       = h23;
        *(__half2*)(crow + 512 + c0)     = l01;   // mixLo
        *(__half2*)(crow + 512 + c0 + 2) = l23;
    }
}

// ---------------- kernel: output GEMM + fused GRU epilogue ----------------------
__global__ __launch_bounds__(128) void tgemm2_kernel(const float* __restrict__ b_out,
                                                     const float* __restrict__ hidden,
                                                     float* __restrict__ out) {
    extern __shared__ char smem[];

    float acc[4][8][4];
#pragma unroll
    for (int mt = 0; mt < 4; mt++)
#pragma unroll
        for (int nt = 0; nt < 8; nt++)
#pragma unroll
            for (int e = 0; e < 4; e++) acc[mt][nt][e] = 0.0f;

    // GEMM over hi columns only (K=512); Cext row stride = 1024
    mma_gemm_main<512>(g_Cext, 1024, g_Wout, 512, smem, acc);

    const int wid = threadIdx.x >> 5, lane = threadIdx.x & 31;
    const int wm = (wid & 1) * 64, wn = (wid >> 1) * 64;
    const int gid = lane >> 2, tig = lane & 3;
#pragma unroll
    for (int mt = 0; mt < 4; mt++) {
        const int rbase = blockIdx.y * 128 + wm + mt * 16 + gid;
#pragma unroll
        for (int nt = 0; nt < 8; nt++) {
            const int c = blockIdx.x * 128 + wn + nt * 8 + 2 * tig;
            float2 bv = *(const float2*)(b_out + c);
#pragma unroll
            for (int half = 0; half < 2; half++) {
                const int r = rbase + half * 8;
                const __half* crow = g_Cext + (size_t)r * 1024;
                __half2 qh2 = *(const __half2*)(crow + 256 + c);
                __half2 ql2 = *(const __half2*)(crow + 768 + c);
                float2 sg2 = *(const float2*)(g_sg + (size_t)r * 256 + c);
                float2 ug2 = *(const float2*)(g_ug + (size_t)r * 256 + c);
                float2 h2  = *(const float2*)(hidden + (size_t)r * 256 + c);
                float q0 = __half2float(qh2.x) + __half2float(ql2.x);
                float q1 = __half2float(qh2.y) + __half2float(ql2.y);
                float v0 = acc[mt][nt][half * 2 + 0] + bv.x;
                float v1 = acc[mt][nt][half * 2 + 1] + bv.y;
                float a0 = tanhf(v0), a1 = tanhf(v1);
                float cu0 = q0 + sg2.x * a0;
                float cu1 = q1 + sg2.y * a1;
                float2 o;
                o.x = cu0 + ug2.x * (h2.x - cu0);
                o.y = cu1 + ug2.y * (h2.y - cu1);
                *(float2*)(out + (size_t)r * 256 + c) = o;
            }
        }
    }
}

// ---------------- launch ---------------------------------------------------------
extern "C" void kernel_launch(void* const* d_in, const int* in_sizes, int n_in,
                              void* d_out, int out_size) {
    const float* input_tensor = (const float*)d_in[0];  // (B, 258)
    const float* hidden       = (const float*)d_in[1];  // (B, 256)
    const float* w_ih         = (const float*)d_in[2];  // (1024, 256)
    const float* b_ih         = (const float*)d_in[3];  // (1024)
    const float* w_hh         = (const float*)d_in[4];  // (1024, 256)
    const float* b_hh         = (const float*)d_in[5];  // (1024)
    const float* w_out        = (const float*)d_in[6];  // (256, 512)
    const float* b_out        = (const float*)d_in[7];  // (256)
    const float* memory       = (const float*)d_in[8];  // (70, 70, 256)
    float* out = (float*)d_out;                         // (B, 256)

    // Host-side, idempotent, not a stream op (capture-safe).
    cudaFuncSetAttribute(aux_gemm_kernel, cudaFuncAttributeMaxDynamicSharedMemorySize, SMEM_BYTES);
    cudaFuncSetAttribute(tgemm1_kernel,  cudaFuncAttributeMaxDynamicSharedMemorySize, SMEM_BYTES);
    cudaFuncSetAttribute(tgemm2_kernel,  cudaFuncAttributeMaxDynamicSharedMemorySize, SMEM_BYTES);

    conv_ah_kernel<<<dim3(8192, 1, 2), 256>>>(input_tensor, hidden);
    conv_w_kernel<<<dim3(512, 1, 4), 256>>>(w_ih, w_hh, w_out);
    conv_bias_kernel<<<4, 256>>>(b_ih, b_hh);
    aux_gemm_kernel<<<dim3(2, 128), 128, SMEM_BYTES>>>(b_hh);
    tgemm1_kernel<<<dim3(8, 128), 128, SMEM_BYTES>>>();
    phaseB_kernel<<<BSZ, 256>>>(input_tensor, memory);
    tgemm2_kernel<<<dim3(2, 128), 128, SMEM_BYTES>>>(b_out, hidden, out);
}

// round 17
// speedup vs baseline: 1.3132x; 1.3132x over previous
#include <cuda_runtime.h>
#include <cuda_fp16.h>
#include <math.h>
#include <stdint.h>

// Problem constants
#define BSZ  16384
#define HD   256
#define GXD  70
#define GYD  70
#define SWIN 2
#define NKW  25   // 5x5 window

// ---------------- scratch (static device memory, no allocations) ----------------
// g_AH row (512): [featHi(256) | hidHi(256)]
// g_W1 rows (1280 x 512): j<1024: [w_ih[j] | w_hh[j]]; 1024+u: [0 | w_hh[512+u]]
// g_gsum row (1280): [r+s sums(1024 cols, gate blocks) | h_n(256)]
// g_Cext row (1024): [mixHi|qHi|mixLo|qLo]; GEMM2 reads cols [0,512)
__device__ __align__(16) __half g_AH  [(size_t)BSZ * 512];
__device__ __align__(16) __half g_W1  [(size_t)1280 * 512];
__device__ __align__(16) __half g_Wout[(size_t)256 * 512];
__device__ __align__(16) __half g_Cext[(size_t)BSZ * 1024];
__device__ float g_gsum[(size_t)BSZ * 1280];
__device__ float g_sg[(size_t)BSZ * 256];
__device__ float g_ug[(size_t)BSZ * 256];
__device__ float g_bc[1280];   // [b_ih+b_hh (1024) | b_hh_n (256)]

__device__ __forceinline__ float sigmoidf_(float x) {
    return 1.0f / (1.0f + expf(-x));
}

__device__ __forceinline__ uint32_t smem_u32(const void* p) {
    uint32_t a;
    asm("{ .reg .u64 t; cvta.to.shared.u64 t, %1; cvt.u32.u64 %0, t; }" : "=r"(a) : "l"(p));
    return a;
}

__device__ __forceinline__ void ldsm_x4(uint32_t addr, uint32_t& r0, uint32_t& r1,
                                        uint32_t& r2, uint32_t& r3) {
    asm volatile("ldmatrix.sync.aligned.m8n8.x4.shared.b16 {%0,%1,%2,%3}, [%4];"
                 : "=r"(r0), "=r"(r1), "=r"(r2), "=r"(r3) : "r"(addr));
}

__device__ __forceinline__ void mma16816(float& d0, float& d1, float& d2, float& d3,
                                         uint32_t a0, uint32_t a1, uint32_t a2, uint32_t a3,
                                         uint32_t b0, uint32_t b1) {
    asm volatile("mma.sync.aligned.m16n8k16.row.col.f32.f16.f16.f32 "
                 "{%0,%1,%2,%3}, {%4,%5,%6,%7}, {%8,%9}, {%0,%1,%2,%3};"
                 : "+f"(d0), "+f"(d1), "+f"(d2), "+f"(d3)
                 : "r"(a0), "r"(a1), "r"(a2), "r"(a3), "r"(b0), "r"(b1));
}

#define CP_ASYNC16(dst, src) \
    asm volatile("cp.async.cg.shared.global [%0], [%1], 16;" :: "r"(dst), "l"(src))
#define CP_COMMIT() asm volatile("cp.async.commit_group;")
#define CP_WAIT2()  asm volatile("cp.async.wait_group 2;")

// Swizzled tile: 128 rows x 128B (64 halves), unit' = unit ^ (row&7). 16KB/tile.
#define TILEB   16384
#define STAGEB  32768   // A tile + B tile
#define NSTAGE  3
#define SMEM_BYTES (NSTAGE * STAGEB)

// ---------------- conversion kernels (fp32 -> fp16 hi) --------------------------
// z=0: feat -> g_AH cols [0,256); z=1: hidden -> g_AH cols [256,512)
__global__ __launch_bounds__(256) void conv_ah_kernel(const float* __restrict__ input_tensor,
                                                      const float* __restrict__ hidden) {
    size_t i = (size_t)blockIdx.x * 256 + threadIdx.x;   // BSZ*128 threads, 2 cols each
    size_t b = i >> 7;
    int c = (int)(i & 127) * 2;
    const float* src; int stride, base;
    if (blockIdx.z == 0) { src = input_tensor; stride = 258; base = 0;   }
    else                 { src = hidden;       stride = 256; base = 256; }
    float2 v = *(const float2*)(src + b * stride + c);
    __half2 hh;
    hh.x = __float2half(v.x);
    hh.y = __float2half(v.y);
    *(__half2*)(g_AH + b * 512 + base + c) = hh;
}

// z=0: w_ih -> W1[:1024][0:256); z=1: w_hh -> W1[:1024][256:512);
// z=2: w_out -> g_Wout; z=3: h_n rows -> W1[1024+u] = [0 | w_hh[512+u]]
__global__ __launch_bounds__(256) void conv_w_kernel(const float* __restrict__ w_ih,
                                                     const float* __restrict__ w_hh,
                                                     const float* __restrict__ w_out) {
    const int sel = blockIdx.z;
    size_t e = ((size_t)blockIdx.x * 256 + threadIdx.x) * 2;
    if (sel <= 1) {
        if (blockIdx.x >= 512) return;       // 1024*256 elems
        int j = (int)(e >> 8), k = (int)(e & 255);
        const float* src = ((sel == 0) ? w_ih : w_hh) + (size_t)j * 256 + k;
        float2 v = *(const float2*)src;
        __half2 hh; hh.x = __float2half(v.x); hh.y = __float2half(v.y);
        *(__half2*)(g_W1 + (size_t)j * 512 + (sel ? 256 : 0) + k) = hh;
    } else if (sel == 2) {
        if (blockIdx.x >= 256) return;       // 256*512 elems
        float2 v = *(const float2*)(w_out + e);
        __half2 hh; hh.x = __float2half(v.x); hh.y = __float2half(v.y);
        *(__half2*)(g_Wout + e) = hh;
    } else {
        if (blockIdx.x >= 256) return;       // 256 rows x 512 cols
        int u = (int)(e >> 9), k = (int)(e & 511);
        __half2 hh;
        if (k < 256) {
            hh.x = __float2half(0.0f); hh.y = __float2half(0.0f);
        } else {
            float2 v = *(const float2*)(w_hh + (size_t)(512 + u) * 256 + (k - 256));
            hh.x = __float2half(v.x); hh.y = __float2half(v.y);
        }
        *(__half2*)(g_W1 + (size_t)(1024 + u) * 512 + k) = hh;
    }
}

__global__ void conv_bias_kernel(const float* __restrict__ b_ih,
                                 const float* __restrict__ b_hh) {
    int i = blockIdx.x * 256 + threadIdx.x;   // 1280 threads
    if (i < 1024) g_bc[i] = b_ih[i] + b_hh[i];
    else          g_bc[i] = b_hh[512 + (i - 1024)];
}

// ---------------- pipelined mma.sync GEMM mainloop (R15-proven) -----------------
// 128 threads, 4 warps in 2(m) x 2(n); warp tile 64x64; CTA tile 128x128.
template <int KEXT>
__device__ __forceinline__ void mma_gemm_main(const __half* __restrict__ A, int lda,
                                              const __half* __restrict__ W, int ldw,
                                              char* smem, float (&acc)[4][8][4]) {
    const int tid = threadIdx.x;
    const int wid = tid >> 5, lane = tid & 31;
    const int wm = (wid & 1) * 64;
    const int wn = (wid >> 1) * 64;
    const uint32_t sbase = smem_u32(smem);

    const int crow0 = tid >> 3, cunit = tid & 7;
    const __half* ga = A + (size_t)(blockIdx.y * 128) * lda + cunit * 8;
    const __half* gw = W + (size_t)(blockIdx.x * 128) * ldw + cunit * 8;

    int rowA[4], rowB[4];
#pragma unroll
    for (int mt = 0; mt < 4; mt++)
        rowA[mt] = wm + mt * 16 + (lane & 8) + (lane & 7);
#pragma unroll
    for (int nt2 = 0; nt2 < 4; nt2++)
        rowB[nt2] = wn + nt2 * 16 + ((lane >> 4) & 1) * 8 + (lane & 7);
    const int uA = lane >> 4;
    const int uB = (lane >> 3) & 1;

    constexpr int NC = KEXT / 64;

    auto issue = [&](int ch) {
        const int s = ch % NSTAGE;
        const uint32_t dA = sbase + s * STAGEB;
        const uint32_t dB = dA + TILEB;
#pragma unroll
        for (int j = 0; j < 8; j++) {
            const int row = crow0 + j * 16;
            const uint32_t off = (uint32_t)row * 128 + (uint32_t)((cunit ^ (row & 7)) * 16);
            CP_ASYNC16(dA + off, ga + (size_t)row * lda + ch * 64);
            CP_ASYNC16(dB + off, gw + (size_t)row * ldw + ch * 64);
        }
        CP_COMMIT();
    };

    issue(0);
    issue(1);
#pragma unroll 1
    for (int ch = 0; ch < NC; ch++) {
        if (ch + 2 < NC) issue(ch + 2); else CP_COMMIT();
        CP_WAIT2();
        __syncthreads();
        const int s = ch % NSTAGE;
        const uint32_t aB = sbase + s * STAGEB;
        const uint32_t bB = aB + TILEB;
#pragma unroll
        for (int ks = 0; ks < 4; ks++) {
            uint32_t a[4][4], b[4][4];
#pragma unroll
            for (int mt = 0; mt < 4; mt++) {
                const int u = ks * 2 + uA;
                const uint32_t addr = aB + (uint32_t)rowA[mt] * 128
                                    + (uint32_t)((u ^ (rowA[mt] & 7)) * 16);
                ldsm_x4(addr, a[mt][0], a[mt][1], a[mt][2], a[mt][3]);
            }
#pragma unroll
            for (int nt2 = 0; nt2 < 4; nt2++) {
                const int u = ks * 2 + uB;
                const uint32_t addr = bB + (uint32_t)rowB[nt2] * 128
                                    + (uint32_t)((u ^ (rowB[nt2] & 7)) * 16);
                ldsm_x4(addr, b[nt2][0], b[nt2][1], b[nt2][2], b[nt2][3]);
            }
#pragma unroll
            for (int mt = 0; mt < 4; mt++)
#pragma unroll
                for (int nt = 0; nt < 8; nt++) {
                    const uint32_t b0 = b[nt >> 1][(nt & 1) * 2 + 0];
                    const uint32_t b1 = b[nt >> 1][(nt & 1) * 2 + 1];
                    mma16816(acc[mt][nt][0], acc[mt][nt][1], acc[mt][nt][2], acc[mt][nt][3],
                             a[mt][0], a[mt][1], a[mt][2], a[mt][3], b0, b1);
                }
        }
        __syncthreads();
    }
}

// ---------------- kernel: combined gate-sum GEMM (N=1280) ----------------------
__global__ __launch_bounds__(128) void tgemm1_kernel() {
    extern __shared__ char smem[];
    float acc[4][8][4];
#pragma unroll
    for (int mt = 0; mt < 4; mt++)
#pragma unroll
        for (int nt = 0; nt < 8; nt++)
#pragma unroll
            for (int e = 0; e < 4; e++) acc[mt][nt][e] = 0.0f;

    mma_gemm_main<512>(g_AH, 512, g_W1, 512, smem, acc);

    const int wid = threadIdx.x >> 5, lane = threadIdx.x & 31;
    const int wm = (wid & 1) * 64, wn = (wid >> 1) * 64;
    const int gid = lane >> 2, tig = lane & 3;
#pragma unroll
    for (int mt = 0; mt < 4; mt++) {
        const int r = blockIdx.y * 128 + wm + mt * 16 + gid;
#pragma unroll
        for (int nt = 0; nt < 8; nt++) {
            const int c = blockIdx.x * 128 + wn + nt * 8 + 2 * tig;
            float2 bv = *(const float2*)(g_bc + c);
            float2 v0 = { acc[mt][nt][0] + bv.x, acc[mt][nt][1] + bv.y };
            float2 v1 = { acc[mt][nt][2] + bv.x, acc[mt][nt][3] + bv.y };
            *(float2*)(g_gsum + (size_t)r * 1280 + c)       = v0;
            *(float2*)(g_gsum + (size_t)(r + 8) * 1280 + c) = v1;
        }
    }
}

// ---------------- kernel: gates + attention over 5x5 context -------------------
// R15 structure; staging loads reduced to 5 columns via summed-gate algebra.
__global__ __launch_bounds__(256) void phaseB_kernel(
    const float* __restrict__ input_tensor,
    const float* __restrict__ memory) {
    const int b = blockIdx.x;
    const int t = threadIdx.x;

    __shared__ __align__(16) float q_s[HD];
    __shared__ __align__(16) float attn_p[NKW][2];
    __shared__ __align__(16) float w_s[NKW];
    __shared__ __align__(16) float mixp[4][HD];

    const float* gs = g_gsum + (size_t)b * 1280;
    float v_r = gs[t];
    float v_i = gs[256 + t];
    float v_n = gs[512 + t];
    float v_s = gs[768 + t];
    float hn  = gs[1024 + t];   // h_n + b_hh_n

    float rg = sigmoidf_(v_r);
    float ug = sigmoidf_(v_i);
    float sg = sigmoidf_(v_s);
    float q  = tanhf(v_n + (rg - 1.0f) * hn);   // = tanh(i_n + rg*h_n) w/ biases
    q_s[t] = q;
    g_sg[(size_t)b * HD + t] = sg;
    g_ug[(size_t)b * HD + t] = ug;

    int gx = (int)input_tensor[(size_t)b * 258 + 256] + SWIN;
    int gy = (int)input_tensor[(size_t)b * 258 + 257] + SWIN;
    gx = min(max(gx, 0), GXD - 1);
    gy = min(max(gy, 0), GYD - 1);

    __syncthreads();   // q_s ready

    // pass 1: fused gather + partial attention dot (float4); 64 threads per k-row
    const int kq  = t >> 6;
    const int cq  = (t & 63) * 4;
    const int lane = t & 31;
    const int sub  = (t >> 5) & 1;
    float4 q4 = *(const float4*)(q_s + cq);
#pragma unroll
    for (int base = 0; base < 28; base += 4) {
        const int k = base + kq;
        if (k < NKW) {               // uniform per warp
            int xi = min(max(gx + k / 5 - SWIN, 0), GXD - 1);
            int yi = min(max(gy + k % 5 - SWIN, 0), GYD - 1);
            float4 v = *(const float4*)(memory + ((size_t)xi * GYD + yi) * HD + cq);
            float part = v.x * q4.x + v.y * q4.y + v.z * q4.z + v.w * q4.w;
#pragma unroll
            for (int off = 16; off; off >>= 1)
                part += __shfl_xor_sync(0xffffffffu, part, off);
            if (lane == 0) attn_p[k][sub] = part;
        }
    }
    __syncthreads();

    // softmax over 25 (one warp), attn==0 -> -inf, NaN -> 0 semantics
    if (t < 32) {
        float v = (lane < NKW) ? (attn_p[lane][0] + attn_p[lane][1]) : -INFINITY;
        if (v == 0.0f) v = -INFINITY;
        float mx = v;
#pragma unroll
        for (int off = 16; off; off >>= 1)
            mx = fmaxf(mx, __shfl_xor_sync(0xffffffffu, mx, off));
        float e = (mx == -INFINITY) ? 0.0f : expf(v - mx);
        float den = e;
#pragma unroll
        for (int off = 16; off; off >>= 1)
            den += __shfl_xor_sync(0xffffffffu, den, off);
        float wv = (den > 0.0f) ? (e / den) : 0.0f;
        if (lane < NKW) w_s[lane] = wv;
    }

    // q-dependent Cext writes (independent of mix)
    __half* crow = g_Cext + (size_t)b * 1024;
    {
        __half qh = __float2half(q);
        __half ql = __float2half(q - __half2float(qh));
        crow[256 + t] = qh;   // qHi
        crow[768 + t] = ql;   // qLo
    }
    __syncthreads();

    // pass 2: re-gather (cache hits) + weighted mix partials per k-group
    {
        float4 m4 = make_float4(0.0f, 0.0f, 0.0f, 0.0f);
#pragma unroll
        for (int base = 0; base < 28; base += 4) {
            const int k = base + kq;
            if (k < NKW) {
                int xi = min(max(gx + k / 5 - SWIN, 0), GXD - 1);
                int yi = min(max(gy + k % 5 - SWIN, 0), GYD - 1);
                float4 v = *(const float4*)(memory + ((size_t)xi * GYD + yi) * HD + cq);
                const float w = w_s[k];
                m4.x = fmaf(w, v.x, m4.x);
                m4.y = fmaf(w, v.y, m4.y);
                m4.z = fmaf(w, v.z, m4.z);
                m4.w = fmaf(w, v.w, m4.w);
            }
        }
        *(float4*)(&mixp[kq][cq]) = m4;
    }
    __syncthreads();

    // combine 4 k-group partials (64 threads) and write mix split
    if (t < 64) {
        const int c0 = t * 4;
        float4 a0 = *(const float4*)(&mixp[0][c0]);
        float4 a1 = *(const float4*)(&mixp[1][c0]);
        float4 a2 = *(const float4*)(&mixp[2][c0]);
        float4 a3 = *(const float4*)(&mixp[3][c0]);
        float mv[4] = { a0.x + a1.x + a2.x + a3.x,
                        a0.y + a1.y + a2.y + a3.y,
                        a0.z + a1.z + a2.z + a3.z,
                        a0.w + a1.w + a2.w + a3.w };
        __half mh[4], ml[4];
#pragma unroll
        for (int e = 0; e < 4; e++) {
            mh[e] = __float2half(mv[e]);
            ml[e] = __float2half(mv[e] - __half2float(mh[e]));
        }
        __half2 h01; h01.x = mh[0]; h01.y = mh[1];
        __half2 h23; h23.x = mh[2]; h23.y = mh[3];
        __half2 l01; l01.x = ml[0]; l01.y = ml[1];
        __half2 l23; l23.x = ml[2]; l23.y = ml[3];
        *(__half2*)(crow + c0)           = h01;   // mixHi
        *(__half2*)(crow + c0 + 2)       = h23;
        *(__half2*)(crow + 512 + c0)     = l01;   // mixLo
        *(__half2*)(crow + 512 + c0 + 2) = l23;
    }
}

// ---------------- kernel: output GEMM + fused GRU epilogue ----------------------
__global__ __launch_bounds__(128) void tgemm2_kernel(const float* __restrict__ b_out,
                                                     const float* __restrict__ hidden,
                                                     float* __restrict__ out) {
    extern __shared__ char smem[];

    float acc[4][8][4];
#pragma unroll
    for (int mt = 0; mt < 4; mt++)
#pragma unroll
        for (int nt = 0; nt < 8; nt++)
#pragma unroll
            for (int e = 0; e < 4; e++) acc[mt][nt][e] = 0.0f;

    // GEMM over hi columns only (K=512); Cext row stride = 1024
    mma_gemm_main<512>(g_Cext, 1024, g_Wout, 512, smem, acc);

    const int wid = threadIdx.x >> 5, lane = threadIdx.x & 31;
    const int wm = (wid & 1) * 64, wn = (wid >> 1) * 64;
    const int gid = lane >> 2, tig = lane & 3;
#pragma unroll
    for (int mt = 0; mt < 4; mt++) {
        const int rbase = blockIdx.y * 128 + wm + mt * 16 + gid;
#pragma unroll
        for (int nt = 0; nt < 8; nt++) {
            const int c = blockIdx.x * 128 + wn + nt * 8 + 2 * tig;
            float2 bv = *(const float2*)(b_out + c);
#pragma unroll
            for (int half = 0; half < 2; half++) {
                const int r = rbase + half * 8;
                const __half* crow = g_Cext + (size_t)r * 1024;
                __half2 qh2 = *(const __half2*)(crow + 256 + c);
                __half2 ql2 = *(const __half2*)(crow + 768 + c);
                float2 sg2 = *(const float2*)(g_sg + (size_t)r * 256 + c);
                float2 ug2 = *(const float2*)(g_ug + (size_t)r * 256 + c);
                float2 h2  = *(const float2*)(hidden + (size_t)r * 256 + c);
                float q0 = __half2float(qh2.x) + __half2float(ql2.x);
                float q1 = __half2float(qh2.y) + __half2float(ql2.y);
                float v0 = acc[mt][nt][half * 2 + 0] + bv.x;
                float v1 = acc[mt][nt][half * 2 + 1] + bv.y;
                float a0 = tanhf(v0), a1 = tanhf(v1);
                float cu0 = q0 + sg2.x * a0;
                float cu1 = q1 + sg2.y * a1;
                float2 o;
                o.x = cu0 + ug2.x * (h2.x - cu0);
                o.y = cu1 + ug2.y * (h2.y - cu1);
                *(float2*)(out + (size_t)r * 256 + c) = o;
            }
        }
    }
}

// ---------------- launch ---------------------------------------------------------
extern "C" void kernel_launch(void* const* d_in, const int* in_sizes, int n_in,
                              void* d_out, int out_size) {
    const float* input_tensor = (const float*)d_in[0];  // (B, 258)
    const float* hidden       = (const float*)d_in[1];  // (B, 256)
    const float* w_ih         = (const float*)d_in[2];  // (1024, 256)
    const float* b_ih         = (const float*)d_in[3];  // (1024)
    const float* w_hh         = (const float*)d_in[4];  // (1024, 256)
    const float* b_hh         = (const float*)d_in[5];  // (1024)
    const float* w_out        = (const float*)d_in[6];  // (256, 512)
    const float* b_out        = (const float*)d_in[7];  // (256)
    const float* memory       = (const float*)d_in[8];  // (70, 70, 256)
    float* out = (float*)d_out;                         // (B, 256)

    // Host-side, idempotent, not a stream op (capture-safe).
    cudaFuncSetAttribute(tgemm1_kernel, cudaFuncAttributeMaxDynamicSharedMemorySize, SMEM_BYTES);
    cudaFuncSetAttribute(tgemm2_kernel, cudaFuncAttributeMaxDynamicSharedMemorySize, SMEM_BYTES);

    conv_ah_kernel<<<dim3(8192, 1, 2), 256>>>(input_tensor, hidden);
    conv_w_kernel<<<dim3(512, 1, 4), 256>>>(w_ih, w_hh, w_out);
    conv_bias_kernel<<<5, 256>>>(b_ih, b_hh);
    tgemm1_kernel<<<dim3(10, 128), 128, SMEM_BYTES>>>();
    phaseB_kernel<<<BSZ, 256>>>(input_tensor, memory);
    tgemm2_kernel<<<dim3(2, 128), 128, SMEM_BYTES>>>(b_out, hidden, out);
}